// round 8
// baseline (speedup 1.0000x reference)
#include <cuda_runtime.h>
#include <cstdint>

// Complex attention, fp16 m16n8k16 mma.sync, 512 threads / 16 warps.
// Warp (rb, kh): GEMM1 -> S[16 rows x 32 keys(kh)]; P staged via smem;
// GEMM2 -> O[16 rows x 32 d(kh)] over all 64 keys.

#define S_LEN   2048
#define DH      64
#define QT      128
#define NT      64
#define NTILES  (S_LEN / NT)
#define THREADS 512
#define NITEMS  512
#define GRID    152
#define ROWB    176                     // 88 halves: conflict-free fragment stride

#define QR_B    0
#define QI_B    (QT * ROWB)                     // 22528
#define K_B     (2 * QT * ROWB)                 // 45056
#define KP(buf, pl) (K_B + (((buf) * 2 + (pl)) * (NT * ROWB)))
#define V_B     (K_B + 4 * NT * ROWB)           // 90112
#define VP(buf, pl) (V_B + (((buf) * 2 + (pl)) * (DH * ROWB)))
#define P_B     (V_B + 4 * DH * ROWB)           // 135168
#define PP(pl)  (P_B + ((pl) * (QT * ROWB)))
#define L_B     (P_B + 2 * QT * ROWB)           // 180224
#define SMEM_BYTES (L_B + 1024)                 // 181248

__device__ unsigned int g_ticket;
__global__ void reset_ticket_kernel() { g_ticket = 0u; }

__device__ __forceinline__ uint32_t pkh(float lo, float hi) {
    uint32_t d; asm("cvt.rn.f16x2.f32 %0, %1, %2;" : "=r"(d) : "f"(hi), "f"(lo)); return d;
}
__device__ __forceinline__ void mma16(float* d, const uint32_t* a, uint32_t b0, uint32_t b1) {
    asm volatile(
        "mma.sync.aligned.m16n8k16.row.col.f32.f16.f16.f32 "
        "{%0,%1,%2,%3}, {%4,%5,%6,%7}, {%8,%9}, {%0,%1,%2,%3};"
        : "+f"(d[0]), "+f"(d[1]), "+f"(d[2]), "+f"(d[3])
        : "r"(a[0]), "r"(a[1]), "r"(a[2]), "r"(a[3]), "r"(b0), "r"(b1));
}

__global__ __launch_bounds__(THREADS, 1)
void cv_attn_h2_kernel(
    const float* __restrict__ qr, const float* __restrict__ qi,
    const float* __restrict__ kr, const float* __restrict__ ki,
    const float* __restrict__ vr, const float* __restrict__ vi,
    float* __restrict__ out, long long plane)
{
    extern __shared__ char sm[];
    __shared__ int s_item;

    const int tid  = threadIdx.x;
    const int w    = tid >> 5;
    const int lane = tid & 31;
    const int g4   = lane >> 2;
    const int j4   = lane & 3;
    const int rb   = w & 7;
    const int kh   = w >> 3;
    const int r0   = rb * 16 + g4;

    // loader maps
    const int kkey = tid >> 3, kdb = (tid & 7) * 8;   // K: 8 d of one key per plane
    const int vpl  = w & 1,    vseg = w >> 1;         // V: plane x key-octet, lane = d-pair
    // fragment/byte bases
    const uint32_t qfo = (uint32_t)(r0 * ROWB + 4 * j4);                // Q / P-load
    const uint32_t kfo = (uint32_t)((kh * 32 + g4) * ROWB + 4 * j4);    // K / Vt
    const uint32_t pso = (uint32_t)(r0 * ROWB + kh * 64 + 4 * j4);      // P store

    for (;;) {
        if (tid == 0) s_item = (int)atomicAdd(&g_ticket, 1u);
        __syncthreads();
        const int item = s_item;
        if (item >= NITEMS) break;

        const int bh = item >> 4;
        const int s0 = (item & 15) * QT;
        const long long bb = (long long)bh * S_LEN * DH;

        // ---- prefetch K(0)/V(0) into regs ----
        float4 ka[2], kb[2];
        float2 vv[8];
        {
            const float* g0 = kr + bb + (long long)kkey * DH + kdb;
            const float* g1 = ki + bb + (long long)kkey * DH + kdb;
            ka[0] = *(const float4*)(g0);  ka[1] = *(const float4*)(g0 + 4);
            kb[0] = *(const float4*)(g1);  kb[1] = *(const float4*)(g1 + 4);
            const float* gv = (vpl ? vi : vr) + bb + (long long)(vseg * 8) * DH + 2 * lane;
            #pragma unroll
            for (int j = 0; j < 8; ++j) vv[j] = *(const float2*)(gv + j * DH);
        }

        // ---- load Q (scaled 1/8) -> half planes ----
        {
            const int qrow = tid >> 2, qd = (tid & 3) * 16;
            #pragma unroll
            for (int pl = 0; pl < 2; ++pl) {
                const float* g = (pl ? qi : qr) + bb + (long long)(s0 + qrow) * DH + qd;
                float4 a[4];
                #pragma unroll
                for (int j = 0; j < 4; ++j) a[j] = *(const float4*)(g + j * 4);
                #pragma unroll
                for (int j = 0; j < 4; ++j) {
                    a[j].x *= 0.125f; a[j].y *= 0.125f; a[j].z *= 0.125f; a[j].w *= 0.125f;
                }
                char* d = sm + (pl ? QI_B : QR_B) + qrow * ROWB + qd * 2;
                uint4 u0 = make_uint4(pkh(a[0].x, a[0].y), pkh(a[0].z, a[0].w),
                                      pkh(a[1].x, a[1].y), pkh(a[1].z, a[1].w));
                uint4 u1 = make_uint4(pkh(a[2].x, a[2].y), pkh(a[2].z, a[2].w),
                                      pkh(a[3].x, a[3].y), pkh(a[3].z, a[3].w));
                *(uint4*)(d) = u0;
                *(uint4*)(d + 16) = u1;
            }
        }

        float ore[4][4], oim[4][4];
        #pragma unroll
        for (int nb = 0; nb < 4; ++nb)
            #pragma unroll
            for (int c = 0; c < 4; ++c) { ore[nb][c] = 0.f; oim[nb][c] = 0.f; }
        float l0 = 0.f, l1 = 0.f;

        for (int t = 0; t < NTILES; ++t) {
            const int buf = t & 1;
            // ---- STS K(t), Vt(t) from regs ----
            {
                char* d0 = sm + KP(buf, 0) + kkey * ROWB + kdb * 2;
                *(uint4*)(d0) = make_uint4(pkh(ka[0].x, ka[0].y), pkh(ka[0].z, ka[0].w),
                                           pkh(ka[1].x, ka[1].y), pkh(ka[1].z, ka[1].w));
                char* d1 = sm + KP(buf, 1) + kkey * ROWB + kdb * 2;
                *(uint4*)(d1) = make_uint4(pkh(kb[0].x, kb[0].y), pkh(kb[0].z, kb[0].w),
                                           pkh(kb[1].x, kb[1].y), pkh(kb[1].z, kb[1].w));
                char* dv = sm + VP(buf, vpl) + (2 * lane) * ROWB + vseg * 16;
                *(uint4*)(dv) = make_uint4(pkh(vv[0].x, vv[1].x), pkh(vv[2].x, vv[3].x),
                                           pkh(vv[4].x, vv[5].x), pkh(vv[6].x, vv[7].x));
                *(uint4*)(dv + ROWB) = make_uint4(pkh(vv[0].y, vv[1].y), pkh(vv[2].y, vv[3].y),
                                                  pkh(vv[4].y, vv[5].y), pkh(vv[6].y, vv[7].y));
            }
            __syncthreads();

            // ---- GEMM1: S[16 x 32] complex (this warp's key half) ----
            float sre[4][4], sim[4][4];
            #pragma unroll
            for (int nb = 0; nb < 4; ++nb)
                #pragma unroll
                for (int c = 0; c < 4; ++c) { sre[nb][c] = 0.f; sim[nb][c] = 0.f; }

            #pragma unroll
            for (int ks = 0; ks < 4; ++ks) {
                uint32_t qa[4], qb[4], nqb[4];
                const char* qp = sm + QR_B + qfo + ks * 32;
                qa[0] = *(const uint32_t*)(qp);
                qa[1] = *(const uint32_t*)(qp + 8 * ROWB);
                qa[2] = *(const uint32_t*)(qp + 16);
                qa[3] = *(const uint32_t*)(qp + 8 * ROWB + 16);
                const char* qip = sm + QI_B + qfo + ks * 32;
                qb[0] = *(const uint32_t*)(qip);
                qb[1] = *(const uint32_t*)(qip + 8 * ROWB);
                qb[2] = *(const uint32_t*)(qip + 16);
                qb[3] = *(const uint32_t*)(qip + 8 * ROWB + 16);
                #pragma unroll
                for (int k = 0; k < 4; ++k) nqb[k] = qb[k] ^ 0x80008000u;

                #pragma unroll
                for (int nb = 0; nb < 4; ++nb) {
                    const char* kp  = sm + KP(buf, 0) + kfo + nb * (8 * ROWB) + ks * 32;
                    const char* kip = sm + KP(buf, 1) + kfo + nb * (8 * ROWB) + ks * 32;
                    uint32_t br0 = *(const uint32_t*)(kp);
                    uint32_t br1 = *(const uint32_t*)(kp + 16);
                    uint32_t bi0 = *(const uint32_t*)(kip);
                    uint32_t bi1 = *(const uint32_t*)(kip + 16);
                    mma16(sre[nb], qa,  br0, br1);
                    mma16(sre[nb], nqb, bi0, bi1);
                    mma16(sim[nb], qa,  bi0, bi1);
                    mma16(sim[nb], qb,  br0, br1);
                }
            }

            // ---- cv-softmax epilogue -> P (fp16) into smem ----
            #pragma unroll
            for (int nb = 0; nb < 4; ++nb) {
                #pragma unroll
                for (int c = 0; c < 4; ++c) {
                    float re = sre[nb][c], im = sim[nb][c];
                    float m2  = fmaxf(fmaf(re, re, im * im), 1e-24f);
                    float inv = rsqrtf(m2);
                    float mag = m2 * inv;
                    float e   = __expf(mag);
                    if (c < 2) l0 += e; else l1 += e;
                    float p = e * inv;
                    sre[nb][c] = re * p;
                    sim[nb][c] = im * p;
                }
                char* pr = sm + PP(0) + pso + nb * 16;
                *(uint32_t*)(pr)            = pkh(sre[nb][0], sre[nb][1]);
                *(uint32_t*)(pr + 8 * ROWB) = pkh(sre[nb][2], sre[nb][3]);
                char* pi = sm + PP(1) + pso + nb * 16;
                *(uint32_t*)(pi)            = pkh(sim[nb][0], sim[nb][1]);
                *(uint32_t*)(pi + 8 * ROWB) = pkh(sim[nb][2], sim[nb][3]);
            }
            __syncthreads();

            // ---- prefetch K(t+1)/V(t+1) (hidden under GEMM2) ----
            if (t + 1 < NTILES) {
                const float* g0 = kr + bb + (long long)((t + 1) * NT + kkey) * DH + kdb;
                const float* g1 = ki + bb + (long long)((t + 1) * NT + kkey) * DH + kdb;
                ka[0] = *(const float4*)(g0);  ka[1] = *(const float4*)(g0 + 4);
                kb[0] = *(const float4*)(g1);  kb[1] = *(const float4*)(g1 + 4);
                const float* gv = (vpl ? vi : vr) + bb
                                + (long long)((t + 1) * NT + vseg * 8) * DH + 2 * lane;
                #pragma unroll
                for (int j = 0; j < 8; ++j) vv[j] = *(const float2*)(gv + j * DH);
            }

            // ---- GEMM2: O[16 x 32 d(kh)] += P @ V over all 64 keys ----
            #pragma unroll
            for (int ks = 0; ks < 4; ++ks) {
                uint32_t pa[4], pb[4], npb[4];
                const char* pp = sm + PP(0) + qfo + ks * 32;
                pa[0] = *(const uint32_t*)(pp);
                pa[1] = *(const uint32_t*)(pp + 8 * ROWB);
                pa[2] = *(const uint32_t*)(pp + 16);
                pa[3] = *(const uint32_t*)(pp + 8 * ROWB + 16);
                const char* pip = sm + PP(1) + qfo + ks * 32;
                pb[0] = *(const uint32_t*)(pip);
                pb[1] = *(const uint32_t*)(pip + 8 * ROWB);
                pb[2] = *(const uint32_t*)(pip + 16);
                pb[3] = *(const uint32_t*)(pip + 8 * ROWB + 16);
                #pragma unroll
                for (int k = 0; k < 4; ++k) npb[k] = pb[k] ^ 0x80008000u;

                #pragma unroll
                for (int nb = 0; nb < 4; ++nb) {
                    const char* vp  = sm + VP(buf, 0) + kfo + nb * (8 * ROWB) + ks * 32;
                    const char* vip = sm + VP(buf, 1) + kfo + nb * (8 * ROWB) + ks * 32;
                    uint32_t vr0 = *(const uint32_t*)(vp);
                    uint32_t vr1 = *(const uint32_t*)(vp + 16);
                    uint32_t vi0 = *(const uint32_t*)(vip);
                    uint32_t vi1 = *(const uint32_t*)(vip + 16);
                    mma16(ore[nb], pa,  vr0, vr1);
                    mma16(ore[nb], npb, vi0, vi1);
                    mma16(oim[nb], pa,  vi0, vi1);
                    mma16(oim[nb], pb,  vr0, vr1);
                }
            }
        }

        // ---- combine partial L across key-halves ----
        l0 += __shfl_xor_sync(~0u, l0, 1); l0 += __shfl_xor_sync(~0u, l0, 2);
        l1 += __shfl_xor_sync(~0u, l1, 1); l1 += __shfl_xor_sync(~0u, l1, 2);
        float* Lp = (float*)(sm + L_B);
        if (j4 == 0) { Lp[kh * 128 + r0] = l0; Lp[kh * 128 + r0 + 8] = l1; }
        __syncthreads();
        const float il0 = 1.0f / (Lp[r0] + Lp[128 + r0]);
        const float il1 = 1.0f / (Lp[r0 + 8] + Lp[128 + r0 + 8]);

        // ---- O / L -> smem stage -> coalesced gmem ----
        float* stg = (float*)sm;            // [128][132]: 0..63 re, 64..127 im
        #pragma unroll
        for (int nb = 0; nb < 4; ++nb) {
            const int d0 = kh * 32 + nb * 8 + 2 * j4;
            stg[ r0      * 132 + d0    ]      = ore[nb][0] * il0;
            stg[ r0      * 132 + d0 + 1]      = ore[nb][1] * il0;
            stg[(r0 + 8) * 132 + d0    ]      = ore[nb][2] * il1;
            stg[(r0 + 8) * 132 + d0 + 1]      = ore[nb][3] * il1;
            stg[ r0      * 132 + 64 + d0]     = oim[nb][0] * il0;
            stg[ r0      * 132 + 64 + d0 + 1] = oim[nb][1] * il0;
            stg[(r0 + 8) * 132 + 64 + d0]     = oim[nb][2] * il1;
            stg[(r0 + 8) * 132 + 64 + d0 + 1] = oim[nb][3] * il1;
        }
        __syncthreads();

        for (int i = tid; i < QT * 32; i += THREADS) {
            const int row = i >> 5, c = i & 31;
            float4 v = *(const float4*)(stg + row * 132 + c * 4);
            if (c < 16)
                *(float4*)(out + bb + (long long)(s0 + row) * DH + c * 4) = v;
            else
                *(float4*)(out + plane + bb + (long long)(s0 + row) * DH + (c - 16) * 4) = v;
        }
        __syncthreads();   // stage consumed before next item's Q store
    }
}

extern "C" void kernel_launch(void* const* d_in, const int* in_sizes, int n_in,
                              void* d_out, int out_size) {
    const float* qr = (const float*)d_in[0];
    const float* qi = (const float*)d_in[1];
    const float* kr = (const float*)d_in[2];
    const float* ki = (const float*)d_in[3];
    const float* vr = (const float*)d_in[4];
    const float* vi = (const float*)d_in[5];

    const long long plane = (long long)in_sizes[0];   // B*H*S*D

    static int configured = 0;
    if (!configured) {
        cudaFuncSetAttribute(cv_attn_h2_kernel,
                             cudaFuncAttributeMaxDynamicSharedMemorySize, SMEM_BYTES);
        configured = 1;
    }

    reset_ticket_kernel<<<1, 1>>>();
    cv_attn_h2_kernel<<<GRID, THREADS, SMEM_BYTES>>>(qr, qi, kr, ki, vr, vi,
                                                     (float*)d_out, plane);
}